// round 16
// baseline (speedup 1.0000x reference)
#include <cuda_runtime.h>
#include <cuda_bf16.h>
#include <math.h>
#include <stdint.h>

#define BB 64
#define QQ 1000
#define DD 512
#define CC 81
#define NK 80
#define KB 5
#define MK 5
#define BQ 64000          // BB*QQ
#define JJ 400            // NK*KB boundary slots per batch
#define DELTA 0.6f
#define INVALID_IDX 0x7fffffff
#define BKCAP 48          // per-(b,label) bucket capacity (mean 6.25)

// ---------------- scratch (device globals; no allocations allowed) ----------------
__device__ uint4 g_embn4[(size_t)BQ * (DD / 8)];     // normalized embeddings, bf16 (65.5 MB)
__device__ uint4 g_protonb4[CC * (DD / 8)];          // normalized prototypes, bf16
__device__ float g_dist2[BQ];
__device__ float g_proto_n[CC * DD];                 // normalized prototypes fp32 (pneg)
__device__ float g_p2[NK];
__device__ float g_pinv[CC];
__device__ int   g_mlist[BQ];
__device__ int   g_mcnt;
__device__ int   g_bktcnt[BB * NK];
__device__ short g_bktq[BB * NK * BKCAP];            // local q ids per (b,label)
__device__ int   g_ulist[BB * 1024];
__device__ int   g_bnd_gemm[BB * JJ];
__device__ unsigned char g_bnd_valid[BB * JJ];
__device__ int   g_ucnt[BB];
__device__ __nv_bfloat16 g_SIMh[(size_t)BB * JJ * QQ];   // 51.2 MB (zero-init BSS)
__device__ int   g_nb[BB * JJ * MK];
__device__ int   g_nbcnt[BB * JJ];
__device__ unsigned char g_sgv[BB * JJ];
__device__ float g_Sm[(size_t)BQ * CC];              // exp(S) for matched rows (20.7 MB)
__device__ float g_posexp[BQ];                       // fp32-exact pos exp, per row n
__device__ float g_colsum[CC];
__device__ float g_possum[CC];
__device__ float g_pneg[CC];
__device__ double g_sul_sum;
__device__ double g_cec_sum;
__device__ int    g_nsg;
__device__ int    g_done;

// ---------------- helpers ----------------
__device__ __forceinline__ uint32_t smem_u32(const void* p) {
    uint32_t a;
    asm("{ .reg .u64 t; cvta.to.shared.u64 t, %1; cvt.u32.u64 %0, t; }" : "=r"(a) : "l"(p));
    return a;
}
__device__ __forceinline__ void ldsm_x4(uint32_t& r0, uint32_t& r1, uint32_t& r2, uint32_t& r3,
                                        uint32_t addr) {
    asm volatile("ldmatrix.sync.aligned.m8n8.x4.shared.b16 {%0,%1,%2,%3}, [%4];"
                 : "=r"(r0), "=r"(r1), "=r"(r2), "=r"(r3) : "r"(addr));
}
__device__ __forceinline__ void mma_16816(float* c, const uint32_t* a, uint32_t b0, uint32_t b1) {
    asm volatile(
        "mma.sync.aligned.m16n8k16.row.col.f32.bf16.bf16.f32 "
        "{%0,%1,%2,%3}, {%4,%5,%6,%7}, {%8,%9}, {%0,%1,%2,%3};"
        : "+f"(c[0]), "+f"(c[1]), "+f"(c[2]), "+f"(c[3])
        : "r"(a[0]), "r"(a[1]), "r"(a[2]), "r"(a[3]), "r"(b0), "r"(b1));
}
#define CP16(sm, gm) asm volatile("cp.async.cg.shared.global [%0], [%1], 16;" :: "r"(sm), "l"(gm))
#define CP_COMMIT()  asm volatile("cp.async.commit_group;" ::: "memory")
#define CP_WAIT0()   asm volatile("cp.async.wait_group 0;" ::: "memory")
#define CP_WAIT1()   asm volatile("cp.async.wait_group 1;" ::: "memory")

__device__ __forceinline__ float bf_lo(uint32_t w) { return __uint_as_float(w << 16); }
__device__ __forceinline__ float bf_hi(uint32_t w) { return __uint_as_float(w & 0xffff0000u); }

// ---------------- top-5 primitives (stable: value desc, index asc) ----------------
__device__ __forceinline__ void lane_ins5(float* v, int* ix, float s, int q) {
    if (s <= v[4]) return;
    int p = 4;
#pragma unroll
    for (int j = 3; j >= 0; j--) if (s > v[j]) p = j;
#pragma unroll
    for (int j = 4; j > 0; j--) if (j > p) { v[j] = v[j - 1]; ix[j] = ix[j - 1]; }
    v[p] = s; ix[p] = q;
}
// tie-break-aware insertion (order-independent result)
__device__ __forceinline__ void ins5_tb(float* v, int* ix, float s, int q) {
    int p = 5;
#pragma unroll
    for (int j = 4; j >= 0; j--) if (s > v[j] || (s == v[j] && q < ix[j])) p = j;
    if (p == 5) return;
#pragma unroll
    for (int j = 4; j > 0; j--) if (j > p) { v[j] = v[j - 1]; ix[j] = ix[j - 1]; }
    v[p] = s; ix[p] = q;
}
__device__ __forceinline__ void warp_merge5(float* v, int* ix, float* ov, int* oi) {
#pragma unroll
    for (int r = 0; r < 5; r++) {
        float bv = v[0]; int bi = ix[0];
#pragma unroll
        for (int o = 16; o; o >>= 1) {
            float tv = __shfl_xor_sync(0xffffffffu, bv, o);
            int   ti = __shfl_xor_sync(0xffffffffu, bi, o);
            if (tv > bv || (tv == bv && ti < bi)) { bv = tv; bi = ti; }
        }
        ov[r] = bv; oi[r] = bi;
        if (ix[0] == bi && bi != INVALID_IDX) {
#pragma unroll
            for (int j = 0; j < 4; j++) { v[j] = v[j + 1]; ix[j] = ix[j + 1]; }
            v[4] = -INFINITY; ix[4] = INVALID_IDX;
        }
    }
}

// ---------------- kernels ----------------
// k_proto also performs global init — one fewer launch
__global__ void k_proto(const float* __restrict__ protos) {
    int c = blockIdx.x, t = threadIdx.x;
    if (c == 0) {
        if (t == 0) { g_mcnt = 0; g_nsg = 0; g_done = 0; g_sul_sum = 0.0; g_cec_sum = 0.0; }
        if (t < BB) g_ucnt[t] = 0;
        if (t < CC) { g_colsum[t] = 0.0f; g_possum[t] = 0.0f; }
    }
    {
        int idx = c * 128 + t;       // CC*128 = 10368 > BB*NK = 5120, single pass
        if (idx < BB * NK) g_bktcnt[idx] = 0;
    }
    const float* row = protos + (size_t)c * DD;
    float s = 0.0f;
    for (int i = t; i < DD; i += 128) { float v = row[i]; s += v * v; }
    for (int o = 16; o; o >>= 1) s += __shfl_xor_sync(0xffffffffu, s, o);
    __shared__ float ws[4];
    if ((t & 31) == 0) ws[t >> 5] = s;
    __syncthreads();
    __shared__ float sinv;
    if (t == 0) {
        float tot = ws[0] + ws[1] + ws[2] + ws[3];
        if (c < NK) g_p2[c] = tot;
        float inv = 1.0f / fmaxf(sqrtf(tot), 1e-12f);
        g_pinv[c] = inv;
        sinv = inv;
    }
    __syncthreads();
    float inv = sinv;
    const float2* r2 = (const float2*)row;
    uint32_t* pb = (uint32_t*)g_protonb4 + c * (DD / 2);
    for (int i = t; i < DD / 2; i += 128) {
        float2 f = r2[i];
        float x = f.x * inv, y = f.y * inv;
        g_proto_n[c * DD + 2 * i] = x;
        g_proto_n[c * DD + 2 * i + 1] = y;
        __nv_bfloat162 h = __floats2bfloat162_rn(x, y);
        pb[i] = *(uint32_t*)&h;
    }
}

// warp per row: norm, bf16 normalized copy, matched dist + exact fp32 pos_exp,
// compaction + per-(b,label) bucket append
__global__ void k_rows(const float* __restrict__ obj, const int* __restrict__ labels,
                       const float* __restrict__ protos) {
    int gw = (blockIdx.x * blockDim.x + threadIdx.x) >> 5;
    int lane = threadIdx.x & 31;
    if (gw >= BQ) return;
    const float2* row = (const float2*)(obj + (size_t)gw * DD);
    float2 v[8];
    float s = 0.0f;
#pragma unroll
    for (int i = 0; i < 8; i++) { v[i] = row[lane + 32 * i]; s += v[i].x * v[i].x + v[i].y * v[i].y; }
#pragma unroll
    for (int o = 16; o; o >>= 1) s += __shfl_xor_sync(0xffffffffu, s, o);
    float inv = 1.0f / fmaxf(sqrtf(s), 1e-12f);
    uint32_t* eb = (uint32_t*)g_embn4 + (size_t)gw * (DD / 2);
#pragma unroll
    for (int i = 0; i < 8; i++) {
        __nv_bfloat162 h = __floats2bfloat162_rn(v[i].x * inv, v[i].y * inv);
        eb[lane + 32 * i] = *(uint32_t*)&h;
    }
    int lab = labels[gw];
    if (lab < NK) {
        const float2* pr = (const float2*)(protos + (size_t)lab * DD);
        float d = 0.0f;
#pragma unroll
        for (int i = 0; i < 8; i++) { float2 p = pr[lane + 32 * i]; d += v[i].x * p.x + v[i].y * p.y; }
#pragma unroll
        for (int o = 16; o; o >>= 1) d += __shfl_xor_sync(0xffffffffu, d, o);
        if (lane == 0) {
            int b = gw / QQ, q = gw - b * QQ;
            g_dist2[gw] = s - 2.0f * d + g_p2[lab];
            g_posexp[gw] = expf(d * inv * g_pinv[lab] * 10.0f);   // exact fp32 S_pos
            int slot = atomicAdd(&g_mcnt, 1);
            g_mlist[slot] = gw;
            int bk = b * NK + lab;
            int s2 = atomicAdd(&g_bktcnt[bk], 1);
            if (s2 < BKCAP) g_bktq[bk * BKCAP + s2] = (short)q;
        }
    } else if (lane == 0) {
        int b = gw / QQ;
        int slot = atomicAdd(&g_ucnt[b], 1);
        g_ulist[b * 1024 + slot] = gw;
    }
}

// thread per (b,k): top-5 matched distances from its bucket (~6 entries)
__global__ void k_bnd() {
    int t = blockIdx.x * blockDim.x + threadIdx.x;
    if (t >= BB * NK) return;
    int b = t / NK;
    int cnt = g_bktcnt[t];
    if (cnt > BKCAP) cnt = BKCAP;
    const short* bq = g_bktq + (size_t)t * BKCAP;
    float v[5] = {-INFINITY, -INFINITY, -INFINITY, -INFINITY, -INFINITY};
    int ix[5] = {INVALID_IDX, INVALID_IDX, INVALID_IDX, INVALID_IDX, INVALID_IDX};
    for (int i = 0; i < cnt; i++) {
        int q = bq[i];
        ins5_tb(v, ix, g_dist2[b * QQ + q], q);
    }
    int base = t * KB;
#pragma unroll
    for (int i = 0; i < 5; i++) {
        bool valid = ix[i] != INVALID_IDX;
        g_bnd_valid[base + i] = valid ? 1 : 0;
        g_bnd_gemm[base + i] = b * QQ + (valid ? ix[i] : 0);
    }
}

// ---------------- bf16 HMMA gather-GEMM, 128x64 tiles, double-buffered cp.async ----------
// mode 0: SIMh[z][m][u] = <embn[bnd], embn[ulist]> (bf16 out)   grid (4, 16, 64)
// mode 1: Sm[m][c]     = exp(10 * <embn[mlist], proton>)        grid (500, 2, 1)
#define ASTRIDE 144
#define BUFSTRIDE 27648
#define SMEM_TOTAL_TG 56320

__device__ __forceinline__ void tg_prefetch(uint32_t sbase, int buf, int ch,
                                            const uint4* __restrict__ Asrc,
                                            const uint4* __restrict__ Bsrc,
                                            const int* aid, const int* bid, int tid) {
    uint32_t Ab = sbase + 1024 + buf * BUFSTRIDE;
    uint32_t Bb = Ab + 18432;
#pragma unroll
    for (int i = 0; i < 4; i++) {
        int idx = tid + i * 256, r = idx >> 3, j = idx & 7;
        CP16(Ab + r * ASTRIDE + j * 16, Asrc + (size_t)aid[r] * 64 + ch * 8 + j);
    }
#pragma unroll
    for (int i = 0; i < 2; i++) {
        int idx = tid + i * 256, r = idx >> 3, j = idx & 7;
        CP16(Bb + r * ASTRIDE + j * 16, Bsrc + (size_t)bid[r] * 64 + ch * 8 + j);
    }
    CP_COMMIT();
}

__global__ void __launch_bounds__(256) k_tgemm(int mode) {
    extern __shared__ unsigned char smem[];
    const int tid = threadIdx.x, wid = tid >> 5, lid = tid & 31;
    const int wm = wid & 3, wn = wid >> 2;           // warp tile: rows wm*32, cols wn*32
    const int z = blockIdx.z;
    const int m0 = blockIdx.x * 128, n0 = blockIdx.y * 64;
    int M, N;
    const uint4 *Asrc, *Bsrc;
    if (mode == 0) {
        M = JJ; N = g_ucnt[z];
        if (n0 >= N) return;
        Asrc = g_embn4; Bsrc = g_embn4;
    } else {
        M = g_mcnt; N = CC;
        if (m0 >= M) return;
        Asrc = g_embn4; Bsrc = g_protonb4;
    }
    int* aid = (int*)smem;
    int* bid = (int*)(smem + 512);
    uint32_t sbase = smem_u32(smem);
    if (tid < 128) {
        int r = m0 + tid;
        int a;
        if (mode == 0) a = g_bnd_gemm[z * JJ + (r < JJ ? r : 0)];
        else a = (r < M) ? g_mlist[r] : g_mlist[0];
        aid[tid] = a;
    } else if (tid < 192) {
        int c = n0 + tid - 128, b0;
        if (mode == 0) b0 = (c < N) ? g_ulist[z * 1024 + c] : g_ulist[z * 1024];
        else b0 = (c < N) ? c : 0;
        bid[tid - 128] = b0;
    }
    __syncthreads();

    // per-lane ldmatrix address components (buffer 0 base; add buf*BUFSTRIDE)
    const uint32_t As0 = sbase + 1024, Bs0 = sbase + 1024 + 18432;
    uint32_t aAddr = As0 + (uint32_t)(wm * 32 + (lid & 15)) * ASTRIDE + ((lid >> 4) * 8) * 2;
    uint32_t bAddr = Bs0 + (uint32_t)(wn * 32 + ((lid & 7) | ((lid >> 4) << 3))) * ASTRIDE
                         + (((lid >> 3) & 1) * 8) * 2;

    float acc[2][4][4];
#pragma unroll
    for (int i = 0; i < 2; i++)
#pragma unroll
        for (int j = 0; j < 4; j++)
#pragma unroll
            for (int e = 0; e < 4; e++) acc[i][j][e] = 0.0f;

    int buf = 0;
    tg_prefetch(sbase, 0, 0, Asrc, Bsrc, aid, bid, tid);
    for (int ch = 0; ch < 8; ch++) {
        if (ch < 7) {
            tg_prefetch(sbase, buf ^ 1, ch + 1, Asrc, Bsrc, aid, bid, tid);
            CP_WAIT1();
        } else {
            CP_WAIT0();
        }
        __syncthreads();
        uint32_t aA = aAddr + buf * BUFSTRIDE, bA = bAddr + buf * BUFSTRIDE;
#pragma unroll
        for (int ks = 0; ks < 4; ks++) {
            uint32_t a[2][4], b[2][4];
#pragma unroll
            for (int mt = 0; mt < 2; mt++)
                ldsm_x4(a[mt][0], a[mt][1], a[mt][2], a[mt][3],
                        aA + mt * 16 * ASTRIDE + ks * 32);
#pragma unroll
            for (int nh = 0; nh < 2; nh++)
                ldsm_x4(b[nh][0], b[nh][1], b[nh][2], b[nh][3],
                        bA + nh * 16 * ASTRIDE + ks * 32);
#pragma unroll
            for (int mt = 0; mt < 2; mt++)
#pragma unroll
                for (int nt = 0; nt < 4; nt++) {
                    int nh = nt >> 1, hi = (nt & 1) << 1;
                    mma_16816(acc[mt][nt], a[mt], b[nh][hi], b[nh][hi + 1]);
                }
        }
        __syncthreads();   // all ldsm reads of `buf` done before it is refilled
        buf ^= 1;
    }

    if (mode == 0) {
        // pack bf16 pairs, transpose through padded smem, coalesced uint32 stores
        uint32_t* sD2 = (uint32_t*)(smem + 1024);   // [128][33]
#pragma unroll
        for (int mt = 0; mt < 2; mt++)
#pragma unroll
            for (int nt = 0; nt < 4; nt++) {
                int r0 = wm * 32 + mt * 16 + (lid >> 2);
                int c2 = wn * 16 + nt * 4 + (lid & 3);
                __nv_bfloat162 h0 = __floats2bfloat162_rn(acc[mt][nt][0], acc[mt][nt][1]);
                __nv_bfloat162 h1 = __floats2bfloat162_rn(acc[mt][nt][2], acc[mt][nt][3]);
                sD2[r0 * 33 + c2] = *(uint32_t*)&h0;
                sD2[(r0 + 8) * 33 + c2] = *(uint32_t*)&h1;
            }
        __syncthreads();
#pragma unroll
        for (int i = 0; i < 16; i++) {
            int idx = tid + i * 256, r = idx >> 5, j = idx & 31;
            int gr = m0 + r, col = n0 + 2 * j;
            if (gr < JJ && col < N) {
                uint32_t val = sD2[r * 33 + j];
                __nv_bfloat16* dst = g_SIMh + (size_t)(z * JJ + gr) * QQ + col;
                if (col + 1 < N) *(uint32_t*)dst = val;
                else dst[0] = ((__nv_bfloat162*)&val)->x;
            }
        }
    } else {
        // direct store with fused exp(10*x)
#pragma unroll
        for (int mt = 0; mt < 2; mt++)
#pragma unroll
            for (int nt = 0; nt < 4; nt++)
#pragma unroll
                for (int e = 0; e < 4; e++) {
                    int gr = m0 + wm * 32 + mt * 16 + (lid >> 2) + ((e >> 1) << 3);
                    int col = n0 + wn * 32 + nt * 8 + (lid & 3) * 2 + (e & 1);
                    if (gr < M && col < CC)
                        g_Sm[(size_t)gr * CC + col] = expf(acc[mt][nt][e] * 10.0f);
                }
    }
}

// warp per (b,j): PASS 1 branchless warp-max; only if max > DELTA run exact top-5.
__global__ void k_simtop() {
    int gw = (blockIdx.x * blockDim.x + threadIdx.x) >> 5;
    int lane = threadIdx.x & 31;
    if (gw >= BB * JJ) return;
    int b = gw / JJ;
    const uint4* s4 = (const uint4*)(g_SIMh + (size_t)gw * QQ);
    int U = g_ucnt[b];
    const int* ul = g_ulist + b * 1024;

    // pass 1: branchless max (beyond-U slots are 0.0 — never > DELTA, safe to include)
    float m0 = -INFINITY, m1 = -INFINITY;
    int nw4 = (U + 7) >> 3;
    for (int i4 = lane; i4 < nw4; i4 += 32) {
        uint4 pk = s4[i4];
        m0 = fmaxf(m0, fmaxf(fmaxf(bf_lo(pk.x), bf_hi(pk.x)), fmaxf(bf_lo(pk.y), bf_hi(pk.y))));
        m1 = fmaxf(m1, fmaxf(fmaxf(bf_lo(pk.z), bf_hi(pk.z)), fmaxf(bf_lo(pk.w), bf_hi(pk.w))));
    }
    float mx = fmaxf(m0, m1);
#pragma unroll
    for (int o = 16; o; o >>= 1) mx = fmaxf(mx, __shfl_xor_sync(0xffffffffu, mx, o));

    if (mx <= DELTA) {   // warp-uniform
        if (lane == 0) {
            g_nbcnt[gw] = 0;
            g_sgv[gw] = 0;
            int* nb = g_nb + gw * MK;
#pragma unroll
            for (int i = 0; i < 5; i++) nb[i] = -1;
        }
        return;
    }

    // slow path: exact stable top-5 (general-case correctness)
    const __nv_bfloat16* srow = g_SIMh + (size_t)gw * QQ;
    float v[5] = {-INFINITY, -INFINITY, -INFINITY, -INFINITY, -INFINITY};
    int ix[5] = {INVALID_IDX, INVALID_IDX, INVALID_IDX, INVALID_IDX, INVALID_IDX};
    for (int u = lane; u < U; u += 32)
        lane_ins5(v, ix, __bfloat162float(srow[u]), u);
    float ov[5]; int oi[5];
    warp_merge5(v, ix, ov, oi);
    if (lane == 0) {
        int cnt = 0;
        int* nb = g_nb + gw * MK;
#pragma unroll
        for (int i = 0; i < 5; i++) {
            bool valid = oi[i] != INVALID_IDX;
            cnt += (valid && ov[i] > DELTA) ? 1 : 0;
            nb[i] = valid ? ul[oi[i]] : -1;
        }
        g_nbcnt[gw] = cnt;
        g_sgv[gw] = (g_bnd_valid[gw] && cnt > 0) ? 1 : 0;
    }
}

// tail dispatcher: blocks [0,500) cecred, [500,581) pneg, [581,645) ce (grid-stride)
__global__ void k_tail(const int* __restrict__ labels, const float* __restrict__ obj,
                       const float* __restrict__ cls_w, const float* __restrict__ cls_b) {
    __shared__ float sh[DD + CC];
    int bx = blockIdx.x, t = threadIdx.x;
    if (bx < 500) {
        // colsum/possum of exp(S): warp-per-row coalesced, register accumulation
        float* scol = sh;
        float* spos = sh + CC;
        int wid = t >> 5, lane = t & 31;
        if (t < CC) { scol[t] = 0.0f; spos[t] = 0.0f; }
        __syncthreads();
        int M = g_mcnt;
        int m0 = bx * 128 + wid * 16;      // 8 warps x 16 rows
        float a0 = 0.0f, a1 = 0.0f, a2 = 0.0f;
        for (int r = 0; r < 16; r++) {
            int m = m0 + r;
            if (m >= M) break;
            const float* srow = g_Sm + (size_t)m * CC;
            a0 += srow[lane];
            a1 += srow[lane + 32];
            if (lane + 64 < CC) a2 += srow[lane + 64];
            if (lane == 0) {
                int lab = labels[g_mlist[m]];
                atomicAdd(&spos[lab], srow[lab]);
            }
        }
        atomicAdd(&scol[lane], a0);
        atomicAdd(&scol[lane + 32], a1);
        if (lane + 64 < CC) atomicAdd(&scol[lane + 64], a2);
        __syncthreads();
        if (t < CC) {
            if (scol[t] != 0.0f) atomicAdd(&g_colsum[t], scol[t]);
            if (spos[t] != 0.0f) atomicAdd(&g_possum[t], spos[t]);
        }
    } else if (bx < 500 + CC) {
        int c2 = bx - 500;
        int lane = t & 31, w = t >> 5;
        const float* pb = g_proto_n + (size_t)c2 * DD;
        if (t == 0) sh[0] = 0.0f;
        __syncthreads();
        float local = 0.0f;
        for (int c1 = w; c1 < CC; c1 += 8) {
            if (c1 == c2) continue;
            const float* pa = g_proto_n + (size_t)c1 * DD;
            float d = 0.0f;
#pragma unroll
            for (int i = 0; i < 16; i++) d += pa[lane + i * 32] * pb[lane + i * 32];
            for (int o = 16; o; o >>= 1) d += __shfl_xor_sync(0xffffffffu, d, o);
            if (lane == 0) local += expf(d * 10.0f);
        }
        if (lane == 0) atomicAdd(&sh[0], local);
        __syncthreads();
        if (t == 0) g_pneg[c2] = sh[0];
    } else {
        // ce: grid-stride over bj; gated on g_sgv (expected: never fires)
        float* gb = sh;
        float* lg = sh + DD;
        for (int bj = bx - 581; bj < BB * JJ; bj += 64) {
            if (!g_sgv[bj]) continue;                  // uniform per block
            int cnt = g_nbcnt[bj];
            float idn = 1.0f / (1.0f + (float)cnt);
            const int* nb = g_nb + bj * MK;
            int bnd = g_bnd_gemm[bj];
            for (int d = t; d < DD; d += 256) {
                float s = obj[(size_t)bnd * DD + d];
                for (int i = 0; i < cnt; i++) s += obj[(size_t)nb[i] * DD + d];
                gb[d] = s * idn;
            }
            __syncthreads();
            if (t < CC) {
                float a = cls_b[t];
                const float* w = cls_w + (size_t)t * DD;
                for (int d = 0; d < DD; d++) a += gb[d] * w[d];
                lg[t] = a;
            }
            __syncthreads();
            if (t == 0) {
                float mx = lg[0];
                for (int c = 1; c < CC; c++) mx = fmaxf(mx, lg[c]);
                float se = 0.0f;
                for (int c = 0; c < CC; c++) se += expf(lg[c] - mx);
                float ce = mx + logf(se) - lg[CC - 1];
                atomicAdd(&g_sul_sum, (double)ce);
                atomicAdd(&g_nsg, 1);
            }
            __syncthreads();
        }
    }
}

// loss + final output: block-level reduce, one double atomic per block, ticket writer
__global__ void k_loss_fin(const int* __restrict__ labels, float* __restrict__ out) {
    __shared__ float wsum[8];
    int t = threadIdx.x;
    int m = blockIdx.x * 256 + t;
    float l = 0.0f;
    if (m < g_mcnt) {
        int n = g_mlist[m];
        int lab = labels[n];
        float E = g_pneg[lab] + g_colsum[lab] - g_possum[lab];
        float pe = g_posexp[n];
        l = -logf(pe / (pe + E + 1e-8f));
    }
    for (int o = 16; o; o >>= 1) l += __shfl_xor_sync(0xffffffffu, l, o);
    if ((t & 31) == 0) wsum[t >> 5] = l;
    __syncthreads();
    if (t == 0) {
        float bs = 0.0f;
        for (int i = 0; i < 8; i++) bs += wsum[i];
        if (bs != 0.0f) atomicAdd(&g_cec_sum, (double)bs);
        __threadfence();
        int ticket = atomicAdd(&g_done, 1);
        if (ticket == (int)gridDim.x - 1) {
            __threadfence();
            int nsg = g_nsg;
            out[0] = (nsg > 0) ? (float)(g_sul_sum / (double)nsg) : 0.0f;
            int mc = g_mcnt;
            out[1] = (mc > 0) ? (float)(g_cec_sum / (double)mc) : 0.0f;
        }
    }
}

// ---------------- launcher ----------------
extern "C" void kernel_launch(void* const* d_in, const int* in_sizes, int n_in,
                              void* d_out, int out_size) {
    const float* obj    = (const float*)d_in[0];
    const float* protos = (const float*)d_in[1];
    const float* cls_w  = (const float*)d_in[2];
    const float* cls_b  = (const float*)d_in[3];
    const int*   labels = (const int*)d_in[4];
    float* out = (float*)d_out;

    cudaFuncSetAttribute(k_tgemm, cudaFuncAttributeMaxDynamicSharedMemorySize, SMEM_TOTAL_TG);

    k_proto<<<CC, 128>>>(protos);                                      // + init
    k_rows<<<BQ / 8, 256>>>(obj, labels, protos);
    k_bnd<<<(BB * NK + 255) / 256, 256>>>();
    k_tgemm<<<dim3(4, 16, BB), 256, SMEM_TOTAL_TG>>>(0);               // SIM (bf16 out)
    k_tgemm<<<dim3((BQ + 127) / 128, 2, 1), 256, SMEM_TOTAL_TG>>>(1);  // exp(S)
    k_simtop<<<BB * JJ / 8, 256>>>();
    k_tail<<<645, 256>>>(labels, obj, cls_w, cls_b);
    k_loss_fin<<<(BQ + 255) / 256, 256>>>(labels, out);
}

// round 17
// speedup vs baseline: 1.2823x; 1.2823x over previous
#include <cuda_runtime.h>
#include <cuda_bf16.h>
#include <math.h>
#include <stdint.h>

#define BB 64
#define QQ 1000
#define DD 512
#define CC 81
#define NK 80
#define KB 5
#define MK 5
#define BQ 64000          // BB*QQ
#define JJ 400            // NK*KB boundary slots per batch
#define DELTA 0.6f
#define INVALID_IDX 0x7fffffff
#define BKCAP 48          // per-(b,label) bucket capacity (mean 6.25)

// ---------------- scratch (device globals; no allocations allowed) ----------------
__device__ uint4 g_embn4[(size_t)BQ * (DD / 8)];     // normalized embeddings, bf16 (65.5 MB)
__device__ uint4 g_protonb4[CC * (DD / 8)];          // normalized prototypes, bf16
__device__ float g_dist2[BQ];
__device__ float g_proto_n[CC * DD];                 // normalized prototypes fp32 (pneg)
__device__ float g_p2[NK];
__device__ float g_pinv[CC];
__device__ int   g_mlist[BQ];
__device__ int   g_mcnt;
__device__ int   g_bktcnt[BB * NK];
__device__ short g_bktq[BB * NK * BKCAP];            // local q ids per (b,label)
__device__ int   g_ulist[BB * 1024];
__device__ int   g_bnd_gemm[BB * JJ];
__device__ unsigned char g_bnd_valid[BB * JJ];
__device__ int   g_ucnt[BB];
__device__ __nv_bfloat16 g_SIMh[(size_t)BB * JJ * QQ];   // 51.2 MB (zero-init BSS)
__device__ int   g_nb[BB * JJ * MK];
__device__ int   g_nbcnt[BB * JJ];
__device__ unsigned char g_sgv[BB * JJ];
__device__ float g_Sm[(size_t)BQ * CC];              // exp(S) for matched rows (20.7 MB)
__device__ float g_posexp[BQ];                       // fp32-exact pos exp, per row n
__device__ float g_colsum[CC];
__device__ float g_possum[CC];
__device__ float g_pneg[CC];
__device__ double g_sul_sum;
__device__ double g_cec_sum;
__device__ int    g_nsg;
__device__ int    g_done;

// ---------------- helpers ----------------
__device__ __forceinline__ uint32_t smem_u32(const void* p) {
    uint32_t a;
    asm("{ .reg .u64 t; cvta.to.shared.u64 t, %1; cvt.u32.u64 %0, t; }" : "=r"(a) : "l"(p));
    return a;
}
__device__ __forceinline__ void ldsm_x4(uint32_t& r0, uint32_t& r1, uint32_t& r2, uint32_t& r3,
                                        uint32_t addr) {
    asm volatile("ldmatrix.sync.aligned.m8n8.x4.shared.b16 {%0,%1,%2,%3}, [%4];"
                 : "=r"(r0), "=r"(r1), "=r"(r2), "=r"(r3) : "r"(addr));
}
__device__ __forceinline__ void mma_16816(float* c, const uint32_t* a, uint32_t b0, uint32_t b1) {
    asm volatile(
        "mma.sync.aligned.m16n8k16.row.col.f32.bf16.bf16.f32 "
        "{%0,%1,%2,%3}, {%4,%5,%6,%7}, {%8,%9}, {%0,%1,%2,%3};"
        : "+f"(c[0]), "+f"(c[1]), "+f"(c[2]), "+f"(c[3])
        : "r"(a[0]), "r"(a[1]), "r"(a[2]), "r"(a[3]), "r"(b0), "r"(b1));
}
#define CP16(sm, gm) asm volatile("cp.async.cg.shared.global [%0], [%1], 16;" :: "r"(sm), "l"(gm))
#define CP_COMMIT()  asm volatile("cp.async.commit_group;" ::: "memory")
#define CP_WAIT0()   asm volatile("cp.async.wait_group 0;" ::: "memory")
#define CP_WAIT1()   asm volatile("cp.async.wait_group 1;" ::: "memory")

__device__ __forceinline__ float bf_lo(uint32_t w) { return __uint_as_float(w << 16); }
__device__ __forceinline__ float bf_hi(uint32_t w) { return __uint_as_float(w & 0xffff0000u); }

// ---------------- top-5 primitives (stable: value desc, index asc) ----------------
__device__ __forceinline__ void lane_ins5(float* v, int* ix, float s, int q) {
    if (s <= v[4]) return;
    int p = 4;
#pragma unroll
    for (int j = 3; j >= 0; j--) if (s > v[j]) p = j;
#pragma unroll
    for (int j = 4; j > 0; j--) if (j > p) { v[j] = v[j - 1]; ix[j] = ix[j - 1]; }
    v[p] = s; ix[p] = q;
}
// tie-break-aware insertion (order-independent result)
__device__ __forceinline__ void ins5_tb(float* v, int* ix, float s, int q) {
    int p = 5;
#pragma unroll
    for (int j = 4; j >= 0; j--) if (s > v[j] || (s == v[j] && q < ix[j])) p = j;
    if (p == 5) return;
#pragma unroll
    for (int j = 4; j > 0; j--) if (j > p) { v[j] = v[j - 1]; ix[j] = ix[j - 1]; }
    v[p] = s; ix[p] = q;
}
__device__ __forceinline__ void warp_merge5(float* v, int* ix, float* ov, int* oi) {
#pragma unroll
    for (int r = 0; r < 5; r++) {
        float bv = v[0]; int bi = ix[0];
#pragma unroll
        for (int o = 16; o; o >>= 1) {
            float tv = __shfl_xor_sync(0xffffffffu, bv, o);
            int   ti = __shfl_xor_sync(0xffffffffu, bi, o);
            if (tv > bv || (tv == bv && ti < bi)) { bv = tv; bi = ti; }
        }
        ov[r] = bv; oi[r] = bi;
        if (ix[0] == bi && bi != INVALID_IDX) {
#pragma unroll
            for (int j = 0; j < 4; j++) { v[j] = v[j + 1]; ix[j] = ix[j + 1]; }
            v[4] = -INFINITY; ix[4] = INVALID_IDX;
        }
    }
}

// ---------------- kernels ----------------
// k_proto also performs global init — one fewer launch
__global__ void k_proto(const float* __restrict__ protos) {
    int c = blockIdx.x, t = threadIdx.x;
    if (c == 0) {
        if (t == 0) { g_mcnt = 0; g_nsg = 0; g_done = 0; g_sul_sum = 0.0; g_cec_sum = 0.0; }
        if (t < BB) g_ucnt[t] = 0;
        if (t < CC) { g_colsum[t] = 0.0f; g_possum[t] = 0.0f; }
    }
    {
        int idx = c * 128 + t;       // CC*128 = 10368 > BB*NK = 5120, single pass
        if (idx < BB * NK) g_bktcnt[idx] = 0;
    }
    const float* row = protos + (size_t)c * DD;
    float s = 0.0f;
    for (int i = t; i < DD; i += 128) { float v = row[i]; s += v * v; }
    for (int o = 16; o; o >>= 1) s += __shfl_xor_sync(0xffffffffu, s, o);
    __shared__ float ws[4];
    if ((t & 31) == 0) ws[t >> 5] = s;
    __syncthreads();
    __shared__ float sinv;
    if (t == 0) {
        float tot = ws[0] + ws[1] + ws[2] + ws[3];
        if (c < NK) g_p2[c] = tot;
        float inv = 1.0f / fmaxf(sqrtf(tot), 1e-12f);
        g_pinv[c] = inv;
        sinv = inv;
    }
    __syncthreads();
    float inv = sinv;
    const float2* r2 = (const float2*)row;
    uint32_t* pb = (uint32_t*)g_protonb4 + c * (DD / 2);
    for (int i = t; i < DD / 2; i += 128) {
        float2 f = r2[i];
        float x = f.x * inv, y = f.y * inv;
        g_proto_n[c * DD + 2 * i] = x;
        g_proto_n[c * DD + 2 * i + 1] = y;
        __nv_bfloat162 h = __floats2bfloat162_rn(x, y);
        pb[i] = *(uint32_t*)&h;
    }
}

// warp per row: norm, bf16 normalized copy, matched dist + exact fp32 pos_exp,
// compaction + per-(b,label) bucket append
__global__ void k_rows(const float* __restrict__ obj, const int* __restrict__ labels,
                       const float* __restrict__ protos) {
    int gw = (blockIdx.x * blockDim.x + threadIdx.x) >> 5;
    int lane = threadIdx.x & 31;
    if (gw >= BQ) return;
    const float2* row = (const float2*)(obj + (size_t)gw * DD);
    float2 v[8];
    float s = 0.0f;
#pragma unroll
    for (int i = 0; i < 8; i++) { v[i] = row[lane + 32 * i]; s += v[i].x * v[i].x + v[i].y * v[i].y; }
#pragma unroll
    for (int o = 16; o; o >>= 1) s += __shfl_xor_sync(0xffffffffu, s, o);
    float inv = 1.0f / fmaxf(sqrtf(s), 1e-12f);
    uint32_t* eb = (uint32_t*)g_embn4 + (size_t)gw * (DD / 2);
#pragma unroll
    for (int i = 0; i < 8; i++) {
        __nv_bfloat162 h = __floats2bfloat162_rn(v[i].x * inv, v[i].y * inv);
        eb[lane + 32 * i] = *(uint32_t*)&h;
    }
    int lab = labels[gw];
    if (lab < NK) {
        const float2* pr = (const float2*)(protos + (size_t)lab * DD);
        float d = 0.0f;
#pragma unroll
        for (int i = 0; i < 8; i++) { float2 p = pr[lane + 32 * i]; d += v[i].x * p.x + v[i].y * p.y; }
#pragma unroll
        for (int o = 16; o; o >>= 1) d += __shfl_xor_sync(0xffffffffu, d, o);
        if (lane == 0) {
            int b = gw / QQ, q = gw - b * QQ;
            g_dist2[gw] = s - 2.0f * d + g_p2[lab];
            g_posexp[gw] = expf(d * inv * g_pinv[lab] * 10.0f);   // exact fp32 S_pos
            int slot = atomicAdd(&g_mcnt, 1);
            g_mlist[slot] = gw;
            int bk = b * NK + lab;
            int s2 = atomicAdd(&g_bktcnt[bk], 1);
            if (s2 < BKCAP) g_bktq[bk * BKCAP + s2] = (short)q;
        }
    } else if (lane == 0) {
        int b = gw / QQ;
        int slot = atomicAdd(&g_ucnt[b], 1);
        g_ulist[b * 1024 + slot] = gw;
    }
}

// thread per (b,k): top-5 matched distances from its bucket (~6 entries)
__global__ void k_bnd() {
    int t = blockIdx.x * blockDim.x + threadIdx.x;
    if (t >= BB * NK) return;
    int b = t / NK;
    int cnt = g_bktcnt[t];
    if (cnt > BKCAP) cnt = BKCAP;
    const short* bq = g_bktq + (size_t)t * BKCAP;
    float v[5] = {-INFINITY, -INFINITY, -INFINITY, -INFINITY, -INFINITY};
    int ix[5] = {INVALID_IDX, INVALID_IDX, INVALID_IDX, INVALID_IDX, INVALID_IDX};
    for (int i = 0; i < cnt; i++) {
        int q = bq[i];
        ins5_tb(v, ix, g_dist2[b * QQ + q], q);
    }
    int base = t * KB;
#pragma unroll
    for (int i = 0; i < 5; i++) {
        bool valid = ix[i] != INVALID_IDX;
        g_bnd_valid[base + i] = valid ? 1 : 0;
        g_bnd_gemm[base + i] = b * QQ + (valid ? ix[i] : 0);
    }
}

// ---------------- bf16 HMMA gather-GEMM, 128x64 tiles, double-buffered cp.async ----------
// mode 0: SIMh[z][m][u] = <embn[bnd], embn[ulist]> (bf16 out)   grid (4, 16, 64)
// mode 1: Sm[m][c]     = exp(10 * <embn[mlist], proton>)        grid (500, 2, 1)
#define ASTRIDE 144
#define BUFSTRIDE 27648
#define SMEM_TOTAL_TG 56320

__device__ __forceinline__ void tg_prefetch(uint32_t sbase, int buf, int ch,
                                            const uint4* __restrict__ Asrc,
                                            const uint4* __restrict__ Bsrc,
                                            const int* aid, const int* bid, int tid) {
    uint32_t Ab = sbase + 1024 + buf * BUFSTRIDE;
    uint32_t Bb = Ab + 18432;
#pragma unroll
    for (int i = 0; i < 4; i++) {
        int idx = tid + i * 256, r = idx >> 3, j = idx & 7;
        CP16(Ab + r * ASTRIDE + j * 16, Asrc + (size_t)aid[r] * 64 + ch * 8 + j);
    }
#pragma unroll
    for (int i = 0; i < 2; i++) {
        int idx = tid + i * 256, r = idx >> 3, j = idx & 7;
        CP16(Bb + r * ASTRIDE + j * 16, Bsrc + (size_t)bid[r] * 64 + ch * 8 + j);
    }
    CP_COMMIT();
}

__global__ void __launch_bounds__(256) k_tgemm(int mode) {
    extern __shared__ unsigned char smem[];
    const int tid = threadIdx.x, wid = tid >> 5, lid = tid & 31;
    const int wm = wid & 3, wn = wid >> 2;           // warp tile: rows wm*32, cols wn*32
    const int z = blockIdx.z;
    const int m0 = blockIdx.x * 128, n0 = blockIdx.y * 64;
    int M, N;
    const uint4 *Asrc, *Bsrc;
    if (mode == 0) {
        M = JJ; N = g_ucnt[z];
        if (n0 >= N) return;
        Asrc = g_embn4; Bsrc = g_embn4;
    } else {
        M = g_mcnt; N = CC;
        if (m0 >= M) return;
        Asrc = g_embn4; Bsrc = g_protonb4;
    }
    int* aid = (int*)smem;
    int* bid = (int*)(smem + 512);
    uint32_t sbase = smem_u32(smem);
    if (tid < 128) {
        int r = m0 + tid;
        int a;
        if (mode == 0) a = g_bnd_gemm[z * JJ + (r < JJ ? r : 0)];
        else a = (r < M) ? g_mlist[r] : g_mlist[0];
        aid[tid] = a;
    } else if (tid < 192) {
        int c = n0 + tid - 128, b0;
        if (mode == 0) b0 = (c < N) ? g_ulist[z * 1024 + c] : g_ulist[z * 1024];
        else b0 = (c < N) ? c : 0;
        bid[tid - 128] = b0;
    }
    __syncthreads();

    // per-lane ldmatrix address components (buffer 0 base; add buf*BUFSTRIDE)
    const uint32_t As0 = sbase + 1024, Bs0 = sbase + 1024 + 18432;
    uint32_t aAddr = As0 + (uint32_t)(wm * 32 + (lid & 15)) * ASTRIDE + ((lid >> 4) * 8) * 2;
    uint32_t bAddr = Bs0 + (uint32_t)(wn * 32 + ((lid & 7) | ((lid >> 4) << 3))) * ASTRIDE
                         + (((lid >> 3) & 1) * 8) * 2;

    float acc[2][4][4];
#pragma unroll
    for (int i = 0; i < 2; i++)
#pragma unroll
        for (int j = 0; j < 4; j++)
#pragma unroll
            for (int e = 0; e < 4; e++) acc[i][j][e] = 0.0f;

    int buf = 0;
    tg_prefetch(sbase, 0, 0, Asrc, Bsrc, aid, bid, tid);
    for (int ch = 0; ch < 8; ch++) {
        if (ch < 7) {
            tg_prefetch(sbase, buf ^ 1, ch + 1, Asrc, Bsrc, aid, bid, tid);
            CP_WAIT1();
        } else {
            CP_WAIT0();
        }
        __syncthreads();
        uint32_t aA = aAddr + buf * BUFSTRIDE, bA = bAddr + buf * BUFSTRIDE;
#pragma unroll
        for (int ks = 0; ks < 4; ks++) {
            uint32_t a[2][4], b[2][4];
#pragma unroll
            for (int mt = 0; mt < 2; mt++)
                ldsm_x4(a[mt][0], a[mt][1], a[mt][2], a[mt][3],
                        aA + mt * 16 * ASTRIDE + ks * 32);
#pragma unroll
            for (int nh = 0; nh < 2; nh++)
                ldsm_x4(b[nh][0], b[nh][1], b[nh][2], b[nh][3],
                        bA + nh * 16 * ASTRIDE + ks * 32);
#pragma unroll
            for (int mt = 0; mt < 2; mt++)
#pragma unroll
                for (int nt = 0; nt < 4; nt++) {
                    int nh = nt >> 1, hi = (nt & 1) << 1;
                    mma_16816(acc[mt][nt], a[mt], b[nh][hi], b[nh][hi + 1]);
                }
        }
        __syncthreads();   // all ldsm reads of `buf` done before it is refilled
        buf ^= 1;
    }

    if (mode == 0) {
        // pack bf16 pairs, transpose through padded smem, coalesced uint32 stores
        uint32_t* sD2 = (uint32_t*)(smem + 1024);   // [128][33]
#pragma unroll
        for (int mt = 0; mt < 2; mt++)
#pragma unroll
            for (int nt = 0; nt < 4; nt++) {
                int r0 = wm * 32 + mt * 16 + (lid >> 2);
                int c2 = wn * 16 + nt * 4 + (lid & 3);
                __nv_bfloat162 h0 = __floats2bfloat162_rn(acc[mt][nt][0], acc[mt][nt][1]);
                __nv_bfloat162 h1 = __floats2bfloat162_rn(acc[mt][nt][2], acc[mt][nt][3]);
                sD2[r0 * 33 + c2] = *(uint32_t*)&h0;
                sD2[(r0 + 8) * 33 + c2] = *(uint32_t*)&h1;
            }
        __syncthreads();
#pragma unroll
        for (int i = 0; i < 16; i++) {
            int idx = tid + i * 256, r = idx >> 5, j = idx & 31;
            int gr = m0 + r, col = n0 + 2 * j;
            if (gr < JJ && col < N) {
                uint32_t val = sD2[r * 33 + j];
                __nv_bfloat16* dst = g_SIMh + (size_t)(z * JJ + gr) * QQ + col;
                if (col + 1 < N) *(uint32_t*)dst = val;
                else dst[0] = ((__nv_bfloat162*)&val)->x;
            }
        }
    } else {
        // direct store with fused exp(10*x)
#pragma unroll
        for (int mt = 0; mt < 2; mt++)
#pragma unroll
            for (int nt = 0; nt < 4; nt++)
#pragma unroll
                for (int e = 0; e < 4; e++) {
                    int gr = m0 + wm * 32 + mt * 16 + (lid >> 2) + ((e >> 1) << 3);
                    int col = n0 + wn * 32 + nt * 8 + (lid & 3) * 2 + (e & 1);
                    if (gr < M && col < CC)
                        g_Sm[(size_t)gr * CC + col] = expf(acc[mt][nt][e] * 10.0f);
                }
    }
}

// warp per (b,j): PASS 1 branchless warp-max; only if max > DELTA run exact top-5.
__global__ void k_simtop() {
    int gw = (blockIdx.x * blockDim.x + threadIdx.x) >> 5;
    int lane = threadIdx.x & 31;
    if (gw >= BB * JJ) return;
    int b = gw / JJ;
    const uint4* s4 = (const uint4*)(g_SIMh + (size_t)gw * QQ);
    int U = g_ucnt[b];
    const int* ul = g_ulist + b * 1024;

    // pass 1: branchless max (beyond-U slots are 0.0 — never > DELTA, safe to include)
    float m0 = -INFINITY, m1 = -INFINITY;
    int nw4 = (U + 7) >> 3;
    for (int i4 = lane; i4 < nw4; i4 += 32) {
        uint4 pk = s4[i4];
        m0 = fmaxf(m0, fmaxf(fmaxf(bf_lo(pk.x), bf_hi(pk.x)), fmaxf(bf_lo(pk.y), bf_hi(pk.y))));
        m1 = fmaxf(m1, fmaxf(fmaxf(bf_lo(pk.z), bf_hi(pk.z)), fmaxf(bf_lo(pk.w), bf_hi(pk.w))));
    }
    float mx = fmaxf(m0, m1);
#pragma unroll
    for (int o = 16; o; o >>= 1) mx = fmaxf(mx, __shfl_xor_sync(0xffffffffu, mx, o));

    if (mx <= DELTA) {   // warp-uniform
        if (lane == 0) {
            g_nbcnt[gw] = 0;
            g_sgv[gw] = 0;
            int* nb = g_nb + gw * MK;
#pragma unroll
            for (int i = 0; i < 5; i++) nb[i] = -1;
        }
        return;
    }

    // slow path: exact stable top-5 (general-case correctness)
    const __nv_bfloat16* srow = g_SIMh + (size_t)gw * QQ;
    float v[5] = {-INFINITY, -INFINITY, -INFINITY, -INFINITY, -INFINITY};
    int ix[5] = {INVALID_IDX, INVALID_IDX, INVALID_IDX, INVALID_IDX, INVALID_IDX};
    for (int u = lane; u < U; u += 32)
        lane_ins5(v, ix, __bfloat162float(srow[u]), u);
    float ov[5]; int oi[5];
    warp_merge5(v, ix, ov, oi);
    if (lane == 0) {
        int cnt = 0;
        int* nb = g_nb + gw * MK;
#pragma unroll
        for (int i = 0; i < 5; i++) {
            bool valid = oi[i] != INVALID_IDX;
            cnt += (valid && ov[i] > DELTA) ? 1 : 0;
            nb[i] = valid ? ul[oi[i]] : -1;
        }
        g_nbcnt[gw] = cnt;
        g_sgv[gw] = (g_bnd_valid[gw] && cnt > 0) ? 1 : 0;
    }
}

// tail dispatcher: blocks [0,500) cecred, [500,581) pneg, [581,645) ce
// ce blocks pre-scan their 400 g_sgv flags IN PARALLEL (2 loads/thread) and only
// walk the serial per-slot path if any flag is set (statistically never).
__global__ void k_tail(const int* __restrict__ labels, const float* __restrict__ obj,
                       const float* __restrict__ cls_w, const float* __restrict__ cls_b) {
    __shared__ float sh[DD + CC];
    int bx = blockIdx.x, t = threadIdx.x;
    if (bx < 500) {
        // colsum/possum of exp(S): warp-per-row coalesced, register accumulation
        float* scol = sh;
        float* spos = sh + CC;
        int wid = t >> 5, lane = t & 31;
        if (t < CC) { scol[t] = 0.0f; spos[t] = 0.0f; }
        __syncthreads();
        int M = g_mcnt;
        int m0 = bx * 128 + wid * 16;      // 8 warps x 16 rows
        float a0 = 0.0f, a1 = 0.0f, a2 = 0.0f;
        for (int r = 0; r < 16; r++) {
            int m = m0 + r;
            if (m >= M) break;
            const float* srow = g_Sm + (size_t)m * CC;
            a0 += srow[lane];
            a1 += srow[lane + 32];
            if (lane + 64 < CC) a2 += srow[lane + 64];
            if (lane == 0) {
                int lab = labels[g_mlist[m]];
                atomicAdd(&spos[lab], srow[lab]);
            }
        }
        atomicAdd(&scol[lane], a0);
        atomicAdd(&scol[lane + 32], a1);
        if (lane + 64 < CC) atomicAdd(&scol[lane + 64], a2);
        __syncthreads();
        if (t < CC) {
            if (scol[t] != 0.0f) atomicAdd(&g_colsum[t], scol[t]);
            if (spos[t] != 0.0f) atomicAdd(&g_possum[t], spos[t]);
        }
    } else if (bx < 500 + CC) {
        int c2 = bx - 500;
        int lane = t & 31, w = t >> 5;
        const float* pb = g_proto_n + (size_t)c2 * DD;
        if (t == 0) sh[0] = 0.0f;
        __syncthreads();
        float local = 0.0f;
        for (int c1 = w; c1 < CC; c1 += 8) {
            if (c1 == c2) continue;
            const float* pa = g_proto_n + (size_t)c1 * DD;
            float d = 0.0f;
#pragma unroll
            for (int i = 0; i < 16; i++) d += pa[lane + i * 32] * pb[lane + i * 32];
            for (int o = 16; o; o >>= 1) d += __shfl_xor_sync(0xffffffffu, d, o);
            if (lane == 0) local += expf(d * 10.0f);
        }
        if (lane == 0) atomicAdd(&sh[0], local);
        __syncthreads();
        if (t == 0) g_pneg[c2] = sh[0];
    } else {
        // ce: 64 blocks, each owns a contiguous 400-slot chunk of g_sgv.
        int start = (bx - 581) * 400;                  // 64 * 400 = 25600 = BB*JJ
        int any = 0;
        for (int j = t; j < 400; j += 256) any |= g_sgv[start + j];
        any = __syncthreads_or(any);
        if (!any) return;                              // fast path: no valid slots
        float* gb = sh;
        float* lg = sh + DD;
        for (int bj = start; bj < start + 400; bj++) {
            if (!g_sgv[bj]) continue;                  // uniform per block
            int cnt = g_nbcnt[bj];
            float idn = 1.0f / (1.0f + (float)cnt);
            const int* nb = g_nb + bj * MK;
            int bnd = g_bnd_gemm[bj];
            for (int d = t; d < DD; d += 256) {
                float s = obj[(size_t)bnd * DD + d];
                for (int i = 0; i < cnt; i++) s += obj[(size_t)nb[i] * DD + d];
                gb[d] = s * idn;
            }
            __syncthreads();
            if (t < CC) {
                float a = cls_b[t];
                const float* w = cls_w + (size_t)t * DD;
                for (int d = 0; d < DD; d++) a += gb[d] * w[d];
                lg[t] = a;
            }
            __syncthreads();
            if (t == 0) {
                float mx = lg[0];
                for (int c = 1; c < CC; c++) mx = fmaxf(mx, lg[c]);
                float se = 0.0f;
                for (int c = 0; c < CC; c++) se += expf(lg[c] - mx);
                float ce = mx + logf(se) - lg[CC - 1];
                atomicAdd(&g_sul_sum, (double)ce);
                atomicAdd(&g_nsg, 1);
            }
            __syncthreads();
        }
    }
}

// loss + final output: block-level reduce, one double atomic per block, ticket writer
__global__ void k_loss_fin(const int* __restrict__ labels, float* __restrict__ out) {
    __shared__ float wsum[8];
    int t = threadIdx.x;
    int m = blockIdx.x * 256 + t;
    float l = 0.0f;
    if (m < g_mcnt) {
        int n = g_mlist[m];
        int lab = labels[n];
        float E = g_pneg[lab] + g_colsum[lab] - g_possum[lab];
        float pe = g_posexp[n];
        l = -logf(pe / (pe + E + 1e-8f));
    }
    for (int o = 16; o; o >>= 1) l += __shfl_xor_sync(0xffffffffu, l, o);
    if ((t & 31) == 0) wsum[t >> 5] = l;
    __syncthreads();
    if (t == 0) {
        float bs = 0.0f;
        for (int i = 0; i < 8; i++) bs += wsum[i];
        if (bs != 0.0f) atomicAdd(&g_cec_sum, (double)bs);
        __threadfence();
        int ticket = atomicAdd(&g_done, 1);
        if (ticket == (int)gridDim.x - 1) {
            __threadfence();
            int nsg = g_nsg;
            out[0] = (nsg > 0) ? (float)(g_sul_sum / (double)nsg) : 0.0f;
            int mc = g_mcnt;
            out[1] = (mc > 0) ? (float)(g_cec_sum / (double)mc) : 0.0f;
        }
    }
}

// ---------------- launcher ----------------
extern "C" void kernel_launch(void* const* d_in, const int* in_sizes, int n_in,
                              void* d_out, int out_size) {
    const float* obj    = (const float*)d_in[0];
    const float* protos = (const float*)d_in[1];
    const float* cls_w  = (const float*)d_in[2];
    const float* cls_b  = (const float*)d_in[3];
    const int*   labels = (const int*)d_in[4];
    float* out = (float*)d_out;

    cudaFuncSetAttribute(k_tgemm, cudaFuncAttributeMaxDynamicSharedMemorySize, SMEM_TOTAL_TG);

    k_proto<<<CC, 128>>>(protos);                                      // + init
    k_rows<<<BQ / 8, 256>>>(obj, labels, protos);
    k_bnd<<<(BB * NK + 255) / 256, 256>>>();
    k_tgemm<<<dim3(4, 16, BB), 256, SMEM_TOTAL_TG>>>(0);               // SIM (bf16 out)
    k_tgemm<<<dim3((BQ + 127) / 128, 2, 1), 256, SMEM_TOTAL_TG>>>(1);  // exp(S)
    k_simtop<<<BB * JJ / 8, 256>>>();
    k_tail<<<645, 256>>>(labels, obj, cls_w, cls_b);
    k_loss_fin<<<(BQ + 255) / 256, 256>>>(labels, out);
}